// round 1
// baseline (speedup 1.0000x reference)
#include <cuda_runtime.h>
#include <math.h>

#define HID 1024
#define VOC 50257
#define SEQ 512

// scratch (device globals — no allocation allowed)
__device__ float g_alog[SEQ];     // attention logits
__device__ float g_aapp[HID];     // attn_applied
__device__ float g_x[HID];        // relu(comb) output
__device__ float g_logits[VOC];   // output logits before log_softmax
__device__ float g_red[2];        // max, log(sum exp)

__device__ __forceinline__ float wsum(float v) {
#pragma unroll
    for (int o = 16; o; o >>= 1) v += __shfl_xor_sync(0xffffffffu, v, o);
    return v;
}
__device__ __forceinline__ float wmax(float v) {
#pragma unroll
    for (int o = 16; o; o >>= 1) v = fmaxf(v, __shfl_xor_sync(0xffffffffu, v, o));
    return v;
}

// K1: attention logits  cat=[embed,h0] @ attn_W.T + attn_b   (64 blocks x 256, 1 warp/row)
__global__ void k_attn(const int* __restrict__ tok, const float* __restrict__ hid,
                       const float* __restrict__ emb, const float* __restrict__ attn_W,
                       const float* __restrict__ attn_b) {
    __shared__ float cat[2 * HID];
    int t = threadIdx.x;
    const float* er = emb + (long)tok[0] * HID;
    for (int i = t; i < HID; i += 256) { cat[i] = er[i]; cat[HID + i] = hid[i]; }
    __syncthreads();
    int w = t >> 5, lane = t & 31;
    int row = blockIdx.x * 8 + w;
    const float4* m = (const float4*)(attn_W + (long)row * 2 * HID);
    const float4* c = (const float4*)cat;
    float s = 0.f;
#pragma unroll
    for (int i = 0; i < 16; i++) {
        float4 a = m[lane + 32 * i], b = c[lane + 32 * i];
        s += a.x * b.x + a.y * b.y + a.z * b.z + a.w * b.w;
    }
    s = wsum(s);
    if (lane == 0) g_alog[row] = s + attn_b[row];
}

// K2: softmax over 512, write attn_weights into d_out tail (1 block x 512)
__global__ void k_softmax(float* __restrict__ out_attn) {
    __shared__ float shm[16], shs[16], bc[2];
    int t = threadIdx.x;
    float v = g_alog[t];
    float m = wmax(v);
    if ((t & 31) == 0) shm[t >> 5] = m;
    __syncthreads();
    if (t < 32) { float x = (t < 16) ? shm[t] : -1e30f; x = wmax(x); if (t == 0) bc[0] = x; }
    __syncthreads();
    float e = expf(v - bc[0]);
    float s = wsum(e);
    if ((t & 31) == 0) shs[t >> 5] = s;
    __syncthreads();
    if (t < 32) { float x = (t < 16) ? shs[t] : 0.f; x = wsum(x); if (t == 0) bc[1] = x; }
    __syncthreads();
    out_attn[t] = e / bc[1];
}

// K3: attn_applied[j] = sum_i w[i] * enc[i][j]   (4 blocks x 256, coalesced over j)
__global__ void k_app(const float* __restrict__ out_attn, const float* __restrict__ enc) {
    __shared__ float w[SEQ];
    int t = threadIdx.x;
    for (int i = t; i < SEQ; i += 256) w[i] = out_attn[i];
    __syncthreads();
    int j = blockIdx.x * 256 + t;
    float s = 0.f;
#pragma unroll 8
    for (int i = 0; i < SEQ; i++) s += w[i] * enc[(long)i * HID + j];
    g_aapp[j] = s;
}

// K4: x = relu([embed, attn_applied] @ comb_W.T + comb_b)  (128 blocks x 256)
__global__ void k_comb(const int* __restrict__ tok, const float* __restrict__ emb,
                       const float* __restrict__ comb_W, const float* __restrict__ comb_b) {
    __shared__ float cat[2 * HID];
    int t = threadIdx.x;
    const float* er = emb + (long)tok[0] * HID;
    for (int i = t; i < HID; i += 256) { cat[i] = er[i]; cat[HID + i] = g_aapp[i]; }
    __syncthreads();
    int w = t >> 5, lane = t & 31;
    int row = blockIdx.x * 8 + w;
    const float4* m = (const float4*)(comb_W + (long)row * 2 * HID);
    const float4* c = (const float4*)cat;
    float s = 0.f;
#pragma unroll
    for (int i = 0; i < 16; i++) {
        float4 a = m[lane + 32 * i], b = c[lane + 32 * i];
        s += a.x * b.x + a.y * b.y + a.z * b.z + a.w * b.w;
    }
    s = wsum(s);
    if (lane == 0) g_x[row] = fmaxf(s + comb_b[row], 0.f);
}

// K5: fused GRU cell. 1024 blocks x 192 (6 warps = 6 dot products per output j)
__global__ void k_gru(const float* __restrict__ hid, const float* __restrict__ W_ih,
                      const float* __restrict__ W_hh, const float* __restrict__ b_ih,
                      const float* __restrict__ b_hh, float* __restrict__ out_h) {
    __shared__ float xs[HID], hs[HID];
    __shared__ float p[6];
    int t = threadIdx.x;
    for (int i = t; i < HID; i += 192) { xs[i] = g_x[i]; hs[i] = hid[i]; }
    __syncthreads();
    int w = t >> 5, lane = t & 31;
    int j = blockIdx.x;
    int g = (w < 3) ? w : (w - 3);
    const float* M = (w < 3) ? W_ih : W_hh;
    const float4* m = (const float4*)(M + (long)(g * HID + j) * HID);
    const float4* v = (const float4*)((w < 3) ? xs : hs);
    float s = 0.f;
#pragma unroll
    for (int i = 0; i < 8; i++) {
        float4 a = m[lane + 32 * i], b = v[lane + 32 * i];
        s += a.x * b.x + a.y * b.y + a.z * b.z + a.w * b.w;
    }
    s = wsum(s);
    if (lane == 0) p[w] = s;
    __syncthreads();
    if (t == 0) {
        float ir = p[0] + b_ih[j],           hr = p[3] + b_hh[j];
        float iz = p[1] + b_ih[HID + j],     hz = p[4] + b_hh[HID + j];
        float in_ = p[2] + b_ih[2 * HID + j], hn = p[5] + b_hh[2 * HID + j];
        float r = 1.f / (1.f + expf(-(ir + hr)));
        float z = 1.f / (1.f + expf(-(iz + hz)));
        float n = tanhf(in_ + r * hn);
        out_h[j] = (1.f - z) * n + z * hid[j];
    }
}

// K6: logits = h_new @ out_W.T + out_b   (dominant: 206 MB stream; 1 warp/row)
__global__ void k_out(const float* __restrict__ out_h, const float* __restrict__ out_W,
                      const float* __restrict__ out_b) {
    __shared__ float h[HID];
    int t = threadIdx.x;
    for (int i = t; i < HID; i += 256) h[i] = out_h[i];
    __syncthreads();
    int w = t >> 5, lane = t & 31;
    int row = blockIdx.x * 8 + w;
    if (row >= VOC) return;
    const float4* m = (const float4*)(out_W + (long)row * HID);
    const float4* c = (const float4*)h;
    float s = 0.f;
#pragma unroll
    for (int i = 0; i < 8; i++) {
        float4 a = m[lane + 32 * i], b = c[lane + 32 * i];
        s += a.x * b.x + a.y * b.y + a.z * b.z + a.w * b.w;
    }
    s = wsum(s);
    if (lane == 0) g_logits[row] = s + out_b[row];
}

// K7: max + log-sum-exp over 50257 logits (1 block x 1024; logits fit L2)
__global__ void k_reduce() {
    __shared__ float shm[32], shs[32];
    int t = threadIdx.x;
    float m = -1e30f;
    for (int i = t; i < VOC; i += 1024) m = fmaxf(m, g_logits[i]);
    m = wmax(m);
    if ((t & 31) == 0) shm[t >> 5] = m;
    __syncthreads();
    if (t < 32) { float x = shm[t]; x = wmax(x); if (t == 0) shm[0] = x; }
    __syncthreads();
    float gmax = shm[0];
    float s = 0.f;
    for (int i = t; i < VOC; i += 1024) s += expf(g_logits[i] - gmax);
    s = wsum(s);
    if ((t & 31) == 0) shs[t >> 5] = s;
    __syncthreads();
    if (t < 32) {
        float x = shs[t]; x = wsum(x);
        if (t == 0) { g_red[0] = gmax; g_red[1] = logf(x); }
    }
}

// K8: logp = logits - max - log(sum)
__global__ void k_logp(float* __restrict__ out) {
    int i = blockIdx.x * 256 + threadIdx.x;
    if (i < VOC) out[i] = g_logits[i] - g_red[0] - g_red[1];
}

extern "C" void kernel_launch(void* const* d_in, const int* in_sizes, int n_in,
                              void* d_out, int out_size) {
    const int*   tok    = (const int*)d_in[0];
    const float* hidden = (const float*)d_in[1];
    const float* enc    = (const float*)d_in[2];
    const float* emb    = (const float*)d_in[3];
    const float* attn_W = (const float*)d_in[4];
    const float* attn_b = (const float*)d_in[5];
    const float* comb_W = (const float*)d_in[6];
    const float* comb_b = (const float*)d_in[7];
    const float* W_ih   = (const float*)d_in[8];
    const float* W_hh   = (const float*)d_in[9];
    const float* b_ih   = (const float*)d_in[10];
    const float* b_hh   = (const float*)d_in[11];
    const float* out_W  = (const float*)d_in[12];
    const float* out_b  = (const float*)d_in[13];

    float* out      = (float*)d_out;         // logp  [50257]
    float* out_h    = out + VOC;             // h_new [1024]
    float* out_attn = out + VOC + HID;       // attn_weights [512]

    k_attn<<<SEQ / 8, 256>>>(tok, hidden, emb, attn_W, attn_b);
    k_softmax<<<1, SEQ>>>(out_attn);
    k_app<<<HID / 256, 256>>>(out_attn, enc);
    k_comb<<<HID / 8, 256>>>(tok, emb, comb_W, comb_b);
    k_gru<<<HID, 192>>>(hidden, W_ih, W_hh, b_ih, b_hh, out_h);
    k_out<<<(VOC + 7) / 8, 256>>>(out_h, out_W, out_b);
    k_reduce<<<1, 1024>>>();
    k_logp<<<(VOC + 255) / 256, 256>>>(out);
}

// round 2
// speedup vs baseline: 1.0818x; 1.0818x over previous
#include <cuda_runtime.h>
#include <math.h>

#define HID 1024
#define VOC 50257
#define SEQ 512

__device__ float g_alog[SEQ];     // attention logits
__device__ float g_aapp[HID];     // attn_applied (atomic-accumulated)
__device__ float g_x[HID];        // relu(comb) output
__device__ float g_logits[VOC];   // logits before log_softmax

__device__ __forceinline__ float wsum(float v) {
#pragma unroll
    for (int o = 16; o; o >>= 1) v += __shfl_xor_sync(0xffffffffu, v, o);
    return v;
}
__device__ __forceinline__ float wmax(float v) {
#pragma unroll
    for (int o = 16; o; o >>= 1) v = fmaxf(v, __shfl_xor_sync(0xffffffffu, v, o));
    return v;
}

// K1: attention logits, split-K x4 (256 blocks x 256 thr; 2 rows/block, 4 warps/row)
__global__ void k_attn(const int* __restrict__ tok, const float* __restrict__ hid,
                       const float* __restrict__ emb, const float* __restrict__ attn_W,
                       const float* __restrict__ attn_b) {
    int t = threadIdx.x;
    if (blockIdx.x < 4) g_aapp[blockIdx.x * 256 + t] = 0.f;   // pre-zero for K2 atomics
    int w = t >> 5, lane = t & 31;
    int gw = blockIdx.x * 8 + w;
    int row = gw >> 2;          // 0..511
    int kc  = gw & 3;           // K chunk of 512 floats
    const float* er = emb + (long)tok[0] * HID;
    const float* base = (kc < 2) ? (er + kc * 512) : (hid + (kc - 2) * 512);
    const float4* m = (const float4*)(attn_W + (long)row * 2 * HID + kc * 512);
    const float4* c = (const float4*)base;
    float s = 0.f;
#pragma unroll
    for (int i = 0; i < 4; i++) {
        float4 a = m[lane + 32 * i], b = c[lane + 32 * i];
        s += a.x * b.x + a.y * b.y + a.z * b.z + a.w * b.w;
    }
    s = wsum(s);
    __shared__ float p[8];
    if (lane == 0) p[w] = s;
    __syncthreads();
    if (t < 2) {
        int r = blockIdx.x * 2 + t;
        g_alog[r] = p[4 * t] + p[4 * t + 1] + p[4 * t + 2] + p[4 * t + 3] + attn_b[r];
    }
}

// K2: softmax(512) recomputed per block + partial attn_applied; grid 16 = 4 j-blocks x 4 i-chunks
__global__ void k_softapp(const float* __restrict__ enc, float* __restrict__ out_attn) {
    int t = threadIdx.x;                   // 256
    __shared__ float w[SEQ];
    __shared__ float red[8];
    __shared__ float bcM, bcS;
    float v0 = g_alog[t], v1 = g_alog[t + 256];
    float m = fmaxf(v0, v1);
    m = wmax(m);
    if ((t & 31) == 0) red[t >> 5] = m;
    __syncthreads();
    if (t < 32) { float x = (t < 8) ? red[t] : -1e30f; x = wmax(x); if (t == 0) bcM = x; }
    __syncthreads();
    float e0 = __expf(v0 - bcM), e1 = __expf(v1 - bcM);
    float s = e0 + e1;
    s = wsum(s);
    if ((t & 31) == 0) red[t >> 5] = s;
    __syncthreads();
    if (t < 32) { float x = (t < 8) ? red[t] : 0.f; x = wsum(x); if (t == 0) bcS = x; }
    __syncthreads();
    float inv = 1.f / bcS;
    w[t] = e0 * inv; w[t + 256] = e1 * inv;
    __syncthreads();
    if (blockIdx.x == 0) { out_attn[t] = w[t]; out_attn[t + 256] = w[t + 256]; }
    int jb = blockIdx.x & 3, ic = blockIdx.x >> 2;
    int j = jb * 256 + t;
    const float* ep = enc + (long)ic * 128 * HID + j;
    float acc = 0.f;
#pragma unroll 8
    for (int i = 0; i < 128; i++) acc += w[ic * 128 + i] * ep[(long)i * HID];
    atomicAdd(&g_aapp[j], acc);
}

// K3: x = relu([embed, attn_applied] @ comb_W.T + b), split-K x4 (512 blocks x 256)
__global__ void k_comb(const int* __restrict__ tok, const float* __restrict__ emb,
                       const float* __restrict__ comb_W, const float* __restrict__ comb_b) {
    int t = threadIdx.x;
    int w = t >> 5, lane = t & 31;
    int gw = blockIdx.x * 8 + w;
    int row = gw >> 2;          // 0..1023
    int kc  = gw & 3;
    const float* er = emb + (long)tok[0] * HID;
    const float* base = (kc < 2) ? (er + kc * 512) : (g_aapp + (kc - 2) * 512);
    const float4* m = (const float4*)(comb_W + (long)row * 2 * HID + kc * 512);
    const float4* c = (const float4*)base;
    float s = 0.f;
#pragma unroll
    for (int i = 0; i < 4; i++) {
        float4 a = m[lane + 32 * i], b = c[lane + 32 * i];
        s += a.x * b.x + a.y * b.y + a.z * b.z + a.w * b.w;
    }
    s = wsum(s);
    __shared__ float p[8];
    if (lane == 0) p[w] = s;
    __syncthreads();
    if (t < 2) {
        int r = blockIdx.x * 2 + t;
        float v = p[4 * t] + p[4 * t + 1] + p[4 * t + 2] + p[4 * t + 3] + comb_b[r];
        g_x[r] = fmaxf(v, 0.f);
    }
}

// K4: fused GRU cell. 1024 blocks x 192 (6 warps = 6 dot products per output j)
__global__ void k_gru(const float* __restrict__ hid, const float* __restrict__ W_ih,
                      const float* __restrict__ W_hh, const float* __restrict__ b_ih,
                      const float* __restrict__ b_hh, float* __restrict__ out_h) {
    __shared__ float xs[HID], hs[HID];
    __shared__ float p[6];
    int t = threadIdx.x;
    for (int i = t; i < HID; i += 192) { xs[i] = g_x[i]; hs[i] = hid[i]; }
    __syncthreads();
    int w = t >> 5, lane = t & 31;
    int j = blockIdx.x;
    int g = (w < 3) ? w : (w - 3);
    const float* M = (w < 3) ? W_ih : W_hh;
    const float4* m = (const float4*)(M + (long)(g * HID + j) * HID);
    const float4* v = (const float4*)((w < 3) ? xs : hs);
    float s = 0.f;
#pragma unroll
    for (int i = 0; i < 8; i++) {
        float4 a = m[lane + 32 * i], b = v[lane + 32 * i];
        s += a.x * b.x + a.y * b.y + a.z * b.z + a.w * b.w;
    }
    s = wsum(s);
    if (lane == 0) p[w] = s;
    __syncthreads();
    if (t == 0) {
        float ir = p[0] + b_ih[j],            hr = p[3] + b_hh[j];
        float iz = p[1] + b_ih[HID + j],      hz = p[4] + b_hh[HID + j];
        float in_ = p[2] + b_ih[2 * HID + j], hn = p[5] + b_hh[2 * HID + j];
        float r = 1.f / (1.f + __expf(-(ir + hr)));
        float z = 1.f / (1.f + __expf(-(iz + hz)));
        float n = tanhf(in_ + r * hn);
        out_h[j] = (1.f - z) * n + z * hid[j];
    }
}

// K5: logits = h_new @ out_W.T + out_b  (206 MB stream; 2 rows/warp for MLP=16)
__global__ void k_out(const float* __restrict__ out_h, const float* __restrict__ out_W,
                      const float* __restrict__ out_b) {
    __shared__ float h[HID];
    int t = threadIdx.x;
    for (int i = t; i < HID; i += 256) h[i] = out_h[i];
    __syncthreads();
    int w = t >> 5, lane = t & 31;
    int r0 = blockIdx.x * 16 + w * 2;
    if (r0 >= VOC) return;
    int r1 = r0 + 1;
    int r1c = (r1 < VOC) ? r1 : r0;
    const float4* c  = (const float4*)h;
    const float4* m0 = (const float4*)(out_W + (long)r0  * HID);
    const float4* m1 = (const float4*)(out_W + (long)r1c * HID);
    float s0 = 0.f, s1 = 0.f;
#pragma unroll
    for (int i = 0; i < 8; i++) {
        float4 b  = c[lane + 32 * i];
        float4 a0 = m0[lane + 32 * i];
        float4 a1 = m1[lane + 32 * i];
        s0 += a0.x * b.x + a0.y * b.y + a0.z * b.z + a0.w * b.w;
        s1 += a1.x * b.x + a1.y * b.y + a1.z * b.z + a1.w * b.w;
    }
    s0 = wsum(s0);
    s1 = wsum(s1);
    if (lane == 0) {
        g_logits[r0] = s0 + out_b[r0];
        if (r1 < VOC) g_logits[r1] = s1 + out_b[r1];
    }
}

// K6: fused online logsumexp + logp write (1 block x 1024; logits are L2-resident)
__global__ void k_finish(float* __restrict__ out) {
    __shared__ float shm[32], shs[32];
    __shared__ float bcM, bcL;
    int t = threadIdx.x;
    float m = -1e30f, s = 0.f;
    for (int i = t; i < VOC; i += 1024) {
        float v = g_logits[i];
        if (v > m) { s = s * __expf(m - v) + 1.f; m = v; }
        else        s += __expf(v - m);
    }
#pragma unroll
    for (int o = 16; o; o >>= 1) {
        float om = __shfl_xor_sync(0xffffffffu, m, o);
        float os = __shfl_xor_sync(0xffffffffu, s, o);
        if (om > m) { s = s * __expf(m - om) + os; m = om; }
        else          s += os * __expf(om - m);
    }
    if ((t & 31) == 0) { shm[t >> 5] = m; shs[t >> 5] = s; }
    __syncthreads();
    if (t == 0) {
        float M = shm[0], S = shs[0];
        for (int i = 1; i < 32; i++) {
            float om = shm[i], os = shs[i];
            if (om > M) { S = S * __expf(M - om) + os; M = om; }
            else          S += os * __expf(om - M);
        }
        bcM = M; bcL = logf(S);
    }
    __syncthreads();
    float M = bcM, L = bcL;
    for (int i = t; i < VOC; i += 1024) out[i] = g_logits[i] - M - L;
}

extern "C" void kernel_launch(void* const* d_in, const int* in_sizes, int n_in,
                              void* d_out, int out_size) {
    const int*   tok    = (const int*)d_in[0];
    const float* hidden = (const float*)d_in[1];
    const float* enc    = (const float*)d_in[2];
    const float* emb    = (const float*)d_in[3];
    const float* attn_W = (const float*)d_in[4];
    const float* attn_b = (const float*)d_in[5];
    const float* comb_W = (const float*)d_in[6];
    const float* comb_b = (const float*)d_in[7];
    const float* W_ih   = (const float*)d_in[8];
    const float* W_hh   = (const float*)d_in[9];
    const float* b_ih   = (const float*)d_in[10];
    const float* b_hh   = (const float*)d_in[11];
    const float* out_W  = (const float*)d_in[12];
    const float* out_b  = (const float*)d_in[13];

    float* out      = (float*)d_out;         // logp  [50257]
    float* out_h    = out + VOC;             // h_new [1024]
    float* out_attn = out + VOC + HID;       // attn_weights [512]

    k_attn<<<256, 256>>>(tok, hidden, emb, attn_W, attn_b);
    k_softapp<<<16, 256>>>(enc, out_attn);
    k_comb<<<512, 256>>>(tok, emb, comb_W, comb_b);
    k_gru<<<1024, 192>>>(hidden, W_ih, W_hh, b_ih, b_hh, out_h);
    k_out<<<(VOC + 15) / 16, 256>>>(out_h, out_W, out_b);
    k_finish<<<1, 1024>>>(out);
}

// round 3
// speedup vs baseline: 1.4089x; 1.3024x over previous
#include <cuda_runtime.h>
#include <math.h>

#define HID 1024
#define VOC 50257
#define SEQ 512

__device__ float g_alog[SEQ];          // attention logits
__device__ float g_w[SEQ];             // softmax weights
__device__ float g_papp[4 * HID];      // partial attn_applied (4 i-chunks)
__device__ float g_x[HID];             // relu(comb) output
__device__ float g_gih[6 * HID];       // [gi_r gi_z gi_n gh_r gh_z gh_n]
__device__ float g_logits[VOC + 3];    // padded for float4
__device__ int   g_ctr1;               // k_attn completion counter
__device__ int   g_ctr2;               // k_gruv completion counter

__device__ __forceinline__ float wsum(float v) {
#pragma unroll
    for (int o = 16; o; o >>= 1) v += __shfl_xor_sync(0xffffffffu, v, o);
    return v;
}
__device__ __forceinline__ float wmax(float v) {
#pragma unroll
    for (int o = 16; o; o >>= 1) v = fmaxf(v, __shfl_xor_sync(0xffffffffu, v, o));
    return v;
}

// K1: attention logits (split-K x4) + softmax fused via completion counter.
// 256 blocks x 256 threads; 2 rows/block, 4 warps/row.
__global__ void k_attn(const int* __restrict__ tok, const float* __restrict__ hid,
                       const float* __restrict__ emb, const float* __restrict__ attn_W,
                       const float* __restrict__ attn_b, float* __restrict__ out_attn) {
    int t = threadIdx.x;
    int w = t >> 5, lane = t & 31;
    int gw = blockIdx.x * 8 + w;
    int row = gw >> 2;
    int kc  = gw & 3;
    const float* er = emb + (long)tok[0] * HID;
    const float* base = (kc < 2) ? (er + kc * 512) : (hid + (kc - 2) * 512);
    const float4* m = (const float4*)(attn_W + (long)row * 2 * HID + kc * 512);
    const float4* c = (const float4*)base;
    float s = 0.f;
#pragma unroll
    for (int i = 0; i < 4; i++) {
        float4 a = m[lane + 32 * i], b = c[lane + 32 * i];
        s += a.x * b.x + a.y * b.y + a.z * b.z + a.w * b.w;
    }
    s = wsum(s);
    __shared__ float p[8];
    __shared__ int s_last;
    if (lane == 0) p[w] = s;
    __syncthreads();
    if (t < 2) {
        int r = blockIdx.x * 2 + t;
        g_alog[r] = p[4 * t] + p[4 * t + 1] + p[4 * t + 2] + p[4 * t + 3] + attn_b[r];
        __threadfence();
    }
    __syncthreads();
    if (t == 0) s_last = (atomicAdd(&g_ctr1, 1) == (int)gridDim.x - 1);
    __syncthreads();
    if (!s_last) return;
    // ---- last block: softmax over 512 logits ----
    __threadfence();
    if (t == 0) g_ctr1 = 0;
    __shared__ float red[8];
    __shared__ float bcM, bcS;
    float v0 = g_alog[t], v1 = g_alog[t + 256];
    float mx = wmax(fmaxf(v0, v1));
    if (lane == 0) red[w] = mx;
    __syncthreads();
    if (t < 32) { float x = (t < 8) ? red[t] : -1e30f; x = wmax(x); if (t == 0) bcM = x; }
    __syncthreads();
    float e0 = __expf(v0 - bcM), e1 = __expf(v1 - bcM);
    float ss = wsum(e0 + e1);
    if (lane == 0) red[w] = ss;
    __syncthreads();
    if (t < 32) { float x = (t < 8) ? red[t] : 0.f; x = wsum(x); if (t == 0) bcS = x; }
    __syncthreads();
    float inv = 1.f / bcS;
    float w0 = e0 * inv, w1 = e1 * inv;
    g_w[t] = w0; g_w[t + 256] = w1;
    out_attn[t] = w0; out_attn[t + 256] = w1;
}

// K2: partial attn_applied. 16 blocks = 4 j-blocks x 4 i-chunks (no atomics).
__global__ void k_app(const float* __restrict__ enc) {
    int t = threadIdx.x;                 // 256
    __shared__ float w[128];
    int jb = blockIdx.x & 3, ic = blockIdx.x >> 2;
    if (t < 128) w[t] = g_w[ic * 128 + t];
    __syncthreads();
    int j = jb * 256 + t;
    const float* ep = enc + (long)ic * 128 * HID + j;
    float acc = 0.f;
#pragma unroll 8
    for (int i = 0; i < 128; i++) acc += w[i] * ep[(long)i * HID];
    g_papp[ic * HID + j] = acc;
}

// K3: x = relu([embed, attn_applied] @ comb_W.T + b), split-K x4 (512 blocks x 256).
// attn_applied summed inline from 4 partials (L2-hot).
__global__ void k_comb(const int* __restrict__ tok, const float* __restrict__ emb,
                       const float* __restrict__ comb_W, const float* __restrict__ comb_b) {
    int t = threadIdx.x;
    int w = t >> 5, lane = t & 31;
    int gw = blockIdx.x * 8 + w;
    int row = gw >> 2;
    int kc  = gw & 3;
    const float4* m = (const float4*)(comb_W + (long)row * 2 * HID + kc * 512);
    float s = 0.f;
    if (kc < 2) {
        const float4* c = (const float4*)(emb + (long)tok[0] * HID + kc * 512);
#pragma unroll
        for (int i = 0; i < 4; i++) {
            float4 a = m[lane + 32 * i], b = c[lane + 32 * i];
            s += a.x * b.x + a.y * b.y + a.z * b.z + a.w * b.w;
        }
    } else {
        const float4* p0 = (const float4*)(g_papp + 0 * HID + (kc - 2) * 512);
        const float4* p1 = (const float4*)(g_papp + 1 * HID + (kc - 2) * 512);
        const float4* p2 = (const float4*)(g_papp + 2 * HID + (kc - 2) * 512);
        const float4* p3 = (const float4*)(g_papp + 3 * HID + (kc - 2) * 512);
#pragma unroll
        for (int i = 0; i < 4; i++) {
            int k = lane + 32 * i;
            float4 a = m[k];
            float4 q0 = p0[k], q1 = p1[k], q2 = p2[k], q3 = p3[k];
            float bx = q0.x + q1.x + q2.x + q3.x;
            float by = q0.y + q1.y + q2.y + q3.y;
            float bz = q0.z + q1.z + q2.z + q3.z;
            float bw = q0.w + q1.w + q2.w + q3.w;
            s += a.x * bx + a.y * by + a.z * bz + a.w * bw;
        }
    }
    s = wsum(s);
    __shared__ float p[8];
    if (lane == 0) p[w] = s;
    __syncthreads();
    if (t < 2) {
        int r = blockIdx.x * 2 + t;
        float v = p[4 * t] + p[4 * t + 1] + p[4 * t + 2] + p[4 * t + 3] + comb_b[r];
        g_x[r] = fmaxf(v, 0.f);
    }
}

// K4: GRU GEMV 6144x1024 (2 rows/warp, 384 blocks x 256) + gate tail in last block.
__global__ void k_gruv(const float* __restrict__ hid, const float* __restrict__ W_ih,
                       const float* __restrict__ W_hh, const float* __restrict__ b_ih,
                       const float* __restrict__ b_hh, float* __restrict__ out_h) {
    __shared__ float vs[HID];
    __shared__ int s_last;
    int t = threadIdx.x;
    bool ih = blockIdx.x < 192;
    const float* vecg = ih ? g_x : hid;
    for (int i = t; i < HID; i += 256) vs[i] = vecg[i];
    __syncthreads();
    int w = t >> 5, lane = t & 31;
    int r0 = blockIdx.x * 16 + w * 2;
    int mr = ih ? r0 : (r0 - 3 * HID);
    const float* base = ih ? W_ih : W_hh;
    const float4* m0 = (const float4*)(base + (long)mr * HID);
    const float4* m1 = (const float4*)(base + (long)(mr + 1) * HID);
    const float4* c  = (const float4*)vs;
    float s0 = 0.f, s1 = 0.f;
#pragma unroll
    for (int i = 0; i < 8; i++) {
        float4 b  = c[lane + 32 * i];
        float4 a0 = __ldcs(m0 + lane + 32 * i);
        float4 a1 = __ldcs(m1 + lane + 32 * i);
        s0 += a0.x * b.x + a0.y * b.y + a0.z * b.z + a0.w * b.w;
        s1 += a1.x * b.x + a1.y * b.y + a1.z * b.z + a1.w * b.w;
    }
    s0 = wsum(s0); s1 = wsum(s1);
    if (lane == 0) {
        g_gih[r0] = s0;
        g_gih[r0 + 1] = s1;
        __threadfence();
    }
    __syncthreads();
    if (t == 0) s_last = (atomicAdd(&g_ctr2, 1) == (int)gridDim.x - 1);
    __syncthreads();
    if (!s_last) return;
    // ---- last block: gate math ----
    __threadfence();
    if (t == 0) g_ctr2 = 0;
    for (int j = t; j < HID; j += 256) {
        float ir  = g_gih[j]            + b_ih[j];
        float iz  = g_gih[HID + j]      + b_ih[HID + j];
        float in_ = g_gih[2 * HID + j]  + b_ih[2 * HID + j];
        float hr  = g_gih[3 * HID + j]  + b_hh[j];
        float hz  = g_gih[4 * HID + j]  + b_hh[HID + j];
        float hn  = g_gih[5 * HID + j]  + b_hh[2 * HID + j];
        float r = 1.f / (1.f + __expf(-(ir + hr)));
        float z = 1.f / (1.f + __expf(-(iz + hz)));
        float n = tanhf(in_ + r * hn);
        out_h[j] = (1.f - z) * n + z * hid[j];
    }
}

// K5: logits = h_new @ out_W.T + out_b  (206 MB stream; 4 rows/warp, MLP=32)
__global__ void k_out(const float* __restrict__ out_h, const float* __restrict__ out_W,
                      const float* __restrict__ out_b) {
    __shared__ float h[HID];
    int t = threadIdx.x;
    for (int i = t; i < HID; i += 256) h[i] = out_h[i];
    __syncthreads();
    int w = t >> 5, lane = t & 31;
    int r0 = blockIdx.x * 32 + w * 4;
    if (r0 >= VOC) return;
    int r1 = min(r0 + 1, VOC - 1);
    int r2 = min(r0 + 2, VOC - 1);
    int r3 = min(r0 + 3, VOC - 1);
    const float4* c  = (const float4*)h;
    const float4* m0 = (const float4*)(out_W + (long)r0 * HID);
    const float4* m1 = (const float4*)(out_W + (long)r1 * HID);
    const float4* m2 = (const float4*)(out_W + (long)r2 * HID);
    const float4* m3 = (const float4*)(out_W + (long)r3 * HID);
    float s0 = 0.f, s1 = 0.f, s2 = 0.f, s3 = 0.f;
#pragma unroll
    for (int i = 0; i < 8; i++) {
        int k = lane + 32 * i;
        float4 b  = c[k];
        float4 a0 = __ldcs(m0 + k);
        float4 a1 = __ldcs(m1 + k);
        float4 a2 = __ldcs(m2 + k);
        float4 a3 = __ldcs(m3 + k);
        s0 += a0.x * b.x + a0.y * b.y + a0.z * b.z + a0.w * b.w;
        s1 += a1.x * b.x + a1.y * b.y + a1.z * b.z + a1.w * b.w;
        s2 += a2.x * b.x + a2.y * b.y + a2.z * b.z + a2.w * b.w;
        s3 += a3.x * b.x + a3.y * b.y + a3.z * b.z + a3.w * b.w;
    }
    s0 = wsum(s0); s1 = wsum(s1); s2 = wsum(s2); s3 = wsum(s3);
    if (lane == 0) {
        g_logits[r0] = s0 + out_b[r0];
        if (r0 + 1 < VOC) g_logits[r0 + 1] = s1 + out_b[r0 + 1];
        if (r0 + 2 < VOC) g_logits[r0 + 2] = s2 + out_b[r0 + 2];
        if (r0 + 3 < VOC) g_logits[r0 + 3] = s3 + out_b[r0 + 3];
    }
}

// K6: fused online logsumexp + logp write (1 block x 1024; logits are L2-resident)
#define N4 12564   // 50256/4 full float4s; element 50256 handled scalar
__global__ void k_finish(float* __restrict__ out) {
    __shared__ float shm[32], shs[32];
    __shared__ float bcM, bcL;
    int t = threadIdx.x;
    const float4* L4 = (const float4*)g_logits;
    float m = -1e30f, s = 0.f;
    for (int i = t; i < N4; i += 1024) {
        float4 v = L4[i];
        float lm = fmaxf(fmaxf(v.x, v.y), fmaxf(v.z, v.w));
        if (lm > m) { s = s * __expf(m - lm); m = lm; }
        s += __expf(v.x - m) + __expf(v.y - m) + __expf(v.z - m) + __expf(v.w - m);
    }
    if (t == 0) {
        float v = g_logits[VOC - 1];
        if (v > m) { s = s * __expf(m - v); m = v; }
        s += __expf(v - m);
    }
#pragma unroll
    for (int o = 16; o; o >>= 1) {
        float om = __shfl_xor_sync(0xffffffffu, m, o);
        float os = __shfl_xor_sync(0xffffffffu, s, o);
        if (om > m) { s = s * __expf(m - om) + os; m = om; }
        else          s += os * __expf(om - m);
    }
    if ((t & 31) == 0) { shm[t >> 5] = m; shs[t >> 5] = s; }
    __syncthreads();
    if (t == 0) {
        float M = shm[0], S = shs[0];
        for (int i = 1; i < 32; i++) {
            float om = shm[i], os = shs[i];
            if (om > M) { S = S * __expf(M - om) + os; M = om; }
            else          S += os * __expf(om - M);
        }
        bcM = M; bcL = logf(S);
    }
    __syncthreads();
    float off = bcM + bcL;
    float4* O4 = (float4*)out;
    for (int i = t; i < N4; i += 1024) {
        float4 v = L4[i];
        v.x -= off; v.y -= off; v.z -= off; v.w -= off;
        O4[i] = v;
    }
    if (t == 0) out[VOC - 1] = g_logits[VOC - 1] - off;
}

extern "C" void kernel_launch(void* const* d_in, const int* in_sizes, int n_in,
                              void* d_out, int out_size) {
    const int*   tok    = (const int*)d_in[0];
    const float* hidden = (const float*)d_in[1];
    const float* enc    = (const float*)d_in[2];
    const float* emb    = (const float*)d_in[3];
    const float* attn_W = (const float*)d_in[4];
    const float* attn_b = (const float*)d_in[5];
    const float* comb_W = (const float*)d_in[6];
    const float* comb_b = (const float*)d_in[7];
    const float* W_ih   = (const float*)d_in[8];
    const float* W_hh   = (const float*)d_in[9];
    const float* b_ih   = (const float*)d_in[10];
    const float* b_hh   = (const float*)d_in[11];
    const float* out_W  = (const float*)d_in[12];
    const float* out_b  = (const float*)d_in[13];

    float* out      = (float*)d_out;         // logp  [50257]
    float* out_h    = out + VOC;             // h_new [1024]
    float* out_attn = out + VOC + HID;       // attn_weights [512]

    k_attn<<<256, 256>>>(tok, hidden, emb, attn_W, attn_b, out_attn);
    k_app<<<16, 256>>>(enc);
    k_comb<<<512, 256>>>(tok, emb, comb_W, comb_b);
    k_gruv<<<384, 256>>>(hidden, W_ih, W_hh, b_ih, b_hh, out_h);
    k_out<<<(VOC + 31) / 32, 256>>>(out_h, out_W, out_b);
    k_finish<<<1, 1024>>>(out);
}